// round 12
// baseline (speedup 1.0000x reference)
#include <cuda_runtime.h>
#include <cuda_fp16.h>
#include <math.h>

#define HIDDEN 128
#define MAXN 50000
#define MAXE 800000
#define NB 112          // persistent blocks (<= SM count -> all co-resident)
#define NT 512          // threads per persistent block

// ---------------- scratch (device globals: no allocation allowed) ----------
__device__ __half   g_zt[(size_t)MAXN * HIDDEN];  // z~ = x@M2^T + c  (fp16)
__device__ int      g_degi[MAXN];                 // in-degree; consumed+zeroed by scan
__device__ float    g_dinv[MAXN];                 // deg^-1/2
__device__ int      g_off[MAXN];                  // CSR starts; after fill = ends
__device__ int      g_edge[MAXE];                 // src per CSR slot (4B)
__device__ float    g_M2[HIDDEN * HIDDEN];        // M2 = W @ W (fp32)
__device__ float    g_c[HIDDEN];                  // c  = W @ b
__device__ int      g_bsum[128];                  // chunk sums for scan
__device__ unsigned g_count;                      // monotonic barrier ticket counter

// ---------------- grid barrier (monotonic generations; replay-safe) ----------
__device__ __forceinline__ void grid_barrier() {
    __syncthreads();
    __threadfence();
    if (threadIdx.x == 0) {
        unsigned ticket = atomicAdd(&g_count, 1u);
        unsigned target = (ticket / NB + 1u) * NB;
        while (*(volatile unsigned*)&g_count < target) __nanosleep(64);
    }
    __syncthreads();
}

// ---------------- fused CSR build: deg -> scan -> prefix -> fill --------------
__global__ void __launch_bounds__(NT)
csr_kernel(const int* __restrict__ src, const int* __restrict__ dst, int e, int n) {
    const int tid = threadIdx.x;
    const int blk = blockIdx.x;

    // phase 1: degree count
    for (int i = blk * NT + tid; i < e; i += NB * NT)
        atomicAdd(&g_degi[dst[i]], 1);
    grid_barrier();

    // phase 2: per-chunk scan (+ dinv, + consume/zero degi)
    __shared__ int sh[NT];
    __shared__ int pre_sh;
    const int nchunk = (n + NT - 1) / NT;   // 98 <= NB
    const int i = blk * NT + tid;
    int v = 0;
    if (blk < nchunk) {
        v = (i < n) ? g_degi[i] : 0;
        if (i < n) {
            g_dinv[i] = rsqrtf((float)v);
            g_degi[i] = 0;                  // reset for next replay
        }
        sh[tid] = v;
        __syncthreads();
        for (int d = 1; d < NT; d <<= 1) {
            int u = (tid >= d) ? sh[tid - d] : 0;
            __syncthreads();
            sh[tid] += u;
            __syncthreads();
        }
        if (i < n) g_off[i] = sh[tid] - v;  // exclusive within chunk
        if (tid == NT - 1) g_bsum[blk] = sh[NT - 1];
    }
    grid_barrier();

    // phase 3: add chunk prefixes
    if (blk < nchunk) {
        if (tid == 0) {
            int s = 0;
            for (int j = 0; j < blk; j++) s += g_bsum[j];
            pre_sh = s;
        }
        __syncthreads();
        if (i < n && blk > 0) g_off[i] += pre_sh;
    }
    grid_barrier();

    // phase 4: CSR fill (cursor-free: starts -> ends)
    for (int k = blk * NT + tid; k < e; k += NB * NT) {
        int s = src[k];
        int pos = atomicAdd(&g_off[dst[k]], 1);
        g_edge[pos] = s;
    }
}

// ---------------- M2 = W @ W and c = W @ b (tiny, side stream, t=0) ----------
__global__ void __launch_bounds__(256)
mat_kernel(const float* __restrict__ W, const float* __restrict__ b) {
    if (blockIdx.x == 16) {
        int j = threadIdx.x;
        if (j < HIDDEN) {
            float acc = 0.f;
            for (int k = 0; k < HIDDEN; k++) acc += W[j * HIDDEN + k] * b[k];
            g_c[j] = acc;
        }
        return;
    }
    __shared__ float Wsh[8][HIDDEN];
    const int jbase = blockIdx.x * 8;
    const int tid = threadIdx.x;
    for (int i = tid; i < 8 * HIDDEN; i += 256)
        Wsh[i >> 7][i & 127] = W[(jbase + (i >> 7)) * HIDDEN + (i & 127)];
    __syncthreads();
    const int m = tid & 127;
    const int half = tid >> 7;
    float acc[4] = {0.f, 0.f, 0.f, 0.f};
    for (int k = 0; k < HIDDEN; k++) {
        float wk = __ldg(&W[k * HIDDEN + m]);
#pragma unroll
        for (int q = 0; q < 4; q++) acc[q] += Wsh[half * 4 + q][k] * wk;
    }
#pragma unroll
    for (int q = 0; q < 4; q++)
        g_M2[(jbase + half * 4 + q) * HIDDEN + m] = acc[q];
}

// ---------------- packed f32x2 helpers ---------------------------------------
__device__ __forceinline__ unsigned long long f32x2_pack(float lo, float hi) {
    unsigned long long r;
    asm("mov.b64 %0, {%1, %2};" : "=l"(r) : "f"(lo), "f"(hi));
    return r;
}
__device__ __forceinline__ void f32x2_fma(unsigned long long& d,
                                          unsigned long long a, unsigned long long b) {
    asm("fma.rn.f32x2 %0, %1, %2, %0;" : "+l"(d) : "l"(a), "l"(b));
}
__device__ __forceinline__ float2 f32x2_unpack(unsigned long long v) {
    float2 r;
    asm("mov.b64 {%0, %1}, %2;" : "=f"(r.x), "=f"(r.y) : "l"(v));
    return r;
}

__device__ __forceinline__ float gelu_exact(float v) {
    return 0.5f * v * (1.0f + erff(v * 0.70710678118654752f));
}

// ---------------- GEMM (side stream, t=0): z~ = x @ M2^T + c, fp16 out -------
// Independent of CSR chain -> overlaps the persistent csr_kernel.
#define GEMM_ROWS 64
#define WT_STRIDE 132
#define AT_STRIDE 66

__global__ void __launch_bounds__(256, 2)
gemmz_kernel(const float* __restrict__ A, const float* __restrict__ M2,
             const float* __restrict__ cvec, int n) {
    extern __shared__ float smem[];
    float* Wt = smem;                          // [k][j], stride 132
    float* At = smem + HIDDEN * WT_STRIDE;     // [k][r], stride 66

    const int tid  = threadIdx.x;
    const int row0 = blockIdx.x * GEMM_ROWS;

    for (int i = tid; i < HIDDEN * HIDDEN; i += 256) {
        int j = i >> 7;
        int k = i & 127;
        Wt[k * WT_STRIDE + j] = M2[i];
    }
    const float4* A4 = reinterpret_cast<const float4*>(A);
    for (int i = tid; i < GEMM_ROWS * 32; i += 256) {
        int r  = i >> 5;
        int c4 = i & 31;
        int gr = row0 + r;
        float4 v = (gr < n) ? A4[(size_t)gr * 32 + c4] : make_float4(0.f, 0.f, 0.f, 0.f);
        At[(4 * c4 + 0) * AT_STRIDE + r] = v.x;
        At[(4 * c4 + 1) * AT_STRIDE + r] = v.y;
        At[(4 * c4 + 2) * AT_STRIDE + r] = v.z;
        At[(4 * c4 + 3) * AT_STRIDE + r] = v.w;
    }
    __syncthreads();

    const int tx = tid & 31;
    const int ty = tid >> 5;

    unsigned long long acc[4][4];
#pragma unroll
    for (int p = 0; p < 4; p++)
#pragma unroll
        for (int c = 0; c < 4; c++) acc[p][c] = 0ull;

    const float* at_base = &At[ty * 8];
    const float* wt_base = &Wt[tx * 4];

#pragma unroll 4
    for (int k = 0; k < HIDDEN; k++) {
        float4 w = *reinterpret_cast<const float4*>(&wt_base[k * WT_STRIDE]);
        unsigned long long w0 = f32x2_pack(w.x, w.x);
        unsigned long long w1 = f32x2_pack(w.y, w.y);
        unsigned long long w2 = f32x2_pack(w.z, w.z);
        unsigned long long w3 = f32x2_pack(w.w, w.w);
        const float* ak = &at_base[k * AT_STRIDE];
        unsigned long long a0 = *reinterpret_cast<const unsigned long long*>(ak + 0);
        unsigned long long a1 = *reinterpret_cast<const unsigned long long*>(ak + 2);
        unsigned long long a2 = *reinterpret_cast<const unsigned long long*>(ak + 4);
        unsigned long long a3 = *reinterpret_cast<const unsigned long long*>(ak + 6);
        f32x2_fma(acc[0][0], a0, w0); f32x2_fma(acc[0][1], a0, w1);
        f32x2_fma(acc[0][2], a0, w2); f32x2_fma(acc[0][3], a0, w3);
        f32x2_fma(acc[1][0], a1, w0); f32x2_fma(acc[1][1], a1, w1);
        f32x2_fma(acc[1][2], a1, w2); f32x2_fma(acc[1][3], a1, w3);
        f32x2_fma(acc[2][0], a2, w0); f32x2_fma(acc[2][1], a2, w1);
        f32x2_fma(acc[2][2], a2, w2); f32x2_fma(acc[2][3], a2, w3);
        f32x2_fma(acc[3][0], a3, w0); f32x2_fma(acc[3][1], a3, w1);
        f32x2_fma(acc[3][2], a3, w2); f32x2_fma(acc[3][3], a3, w3);
    }

    float4 cv = reinterpret_cast<const float4*>(cvec)[tx];
    uint2* zt2 = reinterpret_cast<uint2*>(g_zt);
#pragma unroll
    for (int p = 0; p < 4; p++) {
        int r0 = row0 + ty * 8 + 2 * p;
        float2 c0 = f32x2_unpack(acc[p][0]);
        float2 c1 = f32x2_unpack(acc[p][1]);
        float2 c2 = f32x2_unpack(acc[p][2]);
        float2 c3 = f32x2_unpack(acc[p][3]);
        if (r0 < n) {
            __half2 h01 = __floats2half2_rn(c0.x + cv.x, c1.x + cv.y);
            __half2 h23 = __floats2half2_rn(c2.x + cv.z, c3.x + cv.w);
            uint2 u;
            u.x = *reinterpret_cast<unsigned*>(&h01);
            u.y = *reinterpret_cast<unsigned*>(&h23);
            zt2[(size_t)r0 * 32 + tx] = u;
        }
        if (r0 + 1 < n) {
            __half2 h01 = __floats2half2_rn(c0.y + cv.x, c1.y + cv.y);
            __half2 h23 = __floats2half2_rn(c2.y + cv.z, c3.y + cv.w);
            uint2 u;
            u.x = *reinterpret_cast<unsigned*>(&h01);
            u.y = *reinterpret_cast<unsigned*>(&h23);
            zt2[(size_t)(r0 + 1) * 32 + tx] = u;
        }
    }
}

// ---------------- final: out[i] = gelu(dinv_i * sum_e dinv_s * z~[s] + b) ----
__global__ void __launch_bounds__(256)
gather_out_kernel(const float* __restrict__ bvec, float* __restrict__ out, int n) {
    int warp = (blockIdx.x * 256 + threadIdx.x) >> 5;
    int lane = threadIdx.x & 31;
    if (warp >= n) return;
    int p  = (warp == 0) ? 0 : __ldg(&g_off[warp - 1]);
    int pe = __ldg(&g_off[warp]);
    const uint2* z2 = reinterpret_cast<const uint2*>(g_zt);
    float4 acc = make_float4(0.f, 0.f, 0.f, 0.f);
#pragma unroll 1
    for (; p + 3 < pe; p += 4) {
        int s0 = __ldg(&g_edge[p]);
        int s1 = __ldg(&g_edge[p + 1]);
        int s2 = __ldg(&g_edge[p + 2]);
        int s3 = __ldg(&g_edge[p + 3]);
        float w0 = __ldg(&g_dinv[s0]);
        float w1 = __ldg(&g_dinv[s1]);
        float w2 = __ldg(&g_dinv[s2]);
        float w3 = __ldg(&g_dinv[s3]);
        uint2 u0 = __ldg(&z2[(size_t)s0 * 32 + lane]);
        uint2 u1 = __ldg(&z2[(size_t)s1 * 32 + lane]);
        uint2 u2 = __ldg(&z2[(size_t)s2 * 32 + lane]);
        uint2 u3 = __ldg(&z2[(size_t)s3 * 32 + lane]);
        float2 a0 = __half22float2(*reinterpret_cast<__half2*>(&u0.x));
        float2 b0 = __half22float2(*reinterpret_cast<__half2*>(&u0.y));
        float2 a1 = __half22float2(*reinterpret_cast<__half2*>(&u1.x));
        float2 b1 = __half22float2(*reinterpret_cast<__half2*>(&u1.y));
        float2 a2 = __half22float2(*reinterpret_cast<__half2*>(&u2.x));
        float2 b2 = __half22float2(*reinterpret_cast<__half2*>(&u2.y));
        float2 a3 = __half22float2(*reinterpret_cast<__half2*>(&u3.x));
        float2 b3 = __half22float2(*reinterpret_cast<__half2*>(&u3.y));
        acc.x += w0 * a0.x + w1 * a1.x + w2 * a2.x + w3 * a3.x;
        acc.y += w0 * a0.y + w1 * a1.y + w2 * a2.y + w3 * a3.y;
        acc.z += w0 * b0.x + w1 * b1.x + w2 * b2.x + w3 * b3.x;
        acc.w += w0 * b0.y + w1 * b1.y + w2 * b2.y + w3 * b3.y;
    }
    for (; p < pe; p++) {
        int s0 = __ldg(&g_edge[p]);
        float w0 = __ldg(&g_dinv[s0]);
        uint2 u0 = __ldg(&z2[(size_t)s0 * 32 + lane]);
        float2 a0 = __half22float2(*reinterpret_cast<__half2*>(&u0.x));
        float2 b0 = __half22float2(*reinterpret_cast<__half2*>(&u0.y));
        acc.x += w0 * a0.x; acc.y += w0 * a0.y;
        acc.z += w0 * b0.x; acc.w += w0 * b0.y;
    }
    float di = __ldg(&g_dinv[warp]);
    float4 bv = reinterpret_cast<const float4*>(bvec)[lane];
    float4 o;
    o.x = gelu_exact(di * acc.x + bv.x);
    o.y = gelu_exact(di * acc.y + bv.y);
    o.z = gelu_exact(di * acc.z + bv.z);
    o.w = gelu_exact(di * acc.w + bv.w);
    reinterpret_cast<float4*>(out)[(size_t)warp * 32 + lane] = o;
}

// ---------------- launch -----------------------------------------------------
extern "C" void kernel_launch(void* const* d_in, const int* in_sizes, int n_in,
                              void* d_out, int out_size) {
    const float* x = (const float*)d_in[0];
    const float* W = (const float*)d_in[1];
    const float* b = (const float*)d_in[2];
    const int* ei  = (const int*)d_in[3];

    const int n = in_sizes[0] / HIDDEN;   // 50000
    const int e = in_sizes[3] / 2;        // 800000
    const int* src = ei;
    const int* dst = ei + e;

    float* out = (float*)d_out;

    static float* p_M2 = nullptr;
    static float* p_c  = nullptr;
    static cudaStream_t s2 = nullptr;
    static cudaEvent_t ev_fork = nullptr, ev_join = nullptr;
    if (!p_M2) {
        cudaGetSymbolAddress((void**)&p_M2, g_M2);
        cudaGetSymbolAddress((void**)&p_c, g_c);
        cudaStreamCreateWithFlags(&s2, cudaStreamNonBlocking);
        cudaEventCreateWithFlags(&ev_fork, cudaEventDisableTiming);
        cudaEventCreateWithFlags(&ev_join, cudaEventDisableTiming);
        const size_t smem_bytes = (HIDDEN * WT_STRIDE + HIDDEN * AT_STRIDE) * sizeof(float);
        cudaFuncSetAttribute(gemmz_kernel,
                             cudaFuncAttributeMaxDynamicSharedMemorySize, (int)smem_bytes);
    }
    const size_t smem_bytes = (HIDDEN * WT_STRIDE + HIDDEN * AT_STRIDE) * sizeof(float);

    // ---- side stream: mat -> gemmz from t=0 (independent of CSR) ------------
    cudaEventRecord(ev_fork, 0);
    cudaStreamWaitEvent(s2, ev_fork, 0);
    mat_kernel<<<17, 256, 0, s2>>>(W, b);
    const int gemm_blocks = (n + GEMM_ROWS - 1) / GEMM_ROWS;
    gemmz_kernel<<<gemm_blocks, 256, smem_bytes, s2>>>(x, p_M2, p_c, n);
    cudaEventRecord(ev_join, s2);

    // ---- main stream: fused CSR build (overlaps gemmz) -----------------------
    csr_kernel<<<NB, NT>>>(src, dst, e, n);

    // ---- join: gather needs z~, CSR, dinv ------------------------------------
    cudaStreamWaitEvent(0, ev_join, 0);
    unsigned gthreads = (unsigned)n * 32u;
    gather_out_kernel<<<(gthreads + 255) / 256, 256>>>(b, out, n);
}

// round 13
// speedup vs baseline: 1.0425x; 1.0425x over previous
#include <cuda_runtime.h>
#include <cuda_fp16.h>
#include <math.h>

#define HIDDEN 128
#define MAXN 50000
#define MAXE 800000

// ---------------- scratch (device globals: no allocation allowed) ----------
__device__ __half g_zt[(size_t)MAXN * HIDDEN];  // z' = dinv_s * (x@M2^T + c)  (fp16)
__device__ int    g_degi[MAXN];                 // in-degree (int)
__device__ float  g_dinv[MAXN];                 // deg^-1/2
__device__ int    g_off[MAXN];                  // CSR starts; after fill = ends
__device__ int    g_edge[MAXE];                 // src per CSR slot (4B)
__device__ float  g_M2[HIDDEN * HIDDEN];        // M2 = W @ W (fp32)
__device__ float  g_c[HIDDEN];                  // c  = W @ b
__device__ int    g_bsum[64];                   // block sums for scan

// ---------------- degree (int) ----------------------------------------------
__global__ void deg_kernel(const int* __restrict__ dst, int e) {
    int i = blockIdx.x * blockDim.x + threadIdx.x;
    if (i < e) atomicAdd(&g_degi[dst[i]], 1);
}

// ---------------- 2-kernel scan -> exclusive starts (+ fused deg^-1/2) -------
__global__ void __launch_bounds__(1024)
scan_block_kernel(int n) {
    __shared__ int sh[1024];
    int t = threadIdx.x;
    int i = blockIdx.x * 1024 + t;
    int v = (i < n) ? g_degi[i] : 0;
    if (i < n) g_dinv[i] = rsqrtf((float)v);
    sh[t] = v;
    __syncthreads();
    for (int d = 1; d < 1024; d <<= 1) {
        int u = (t >= d) ? sh[t - d] : 0;
        __syncthreads();
        sh[t] += u;
        __syncthreads();
    }
    if (i < n) g_off[i] = sh[t] - v;           // exclusive within block
    if (t == 1023) g_bsum[blockIdx.x] = sh[1023];
}

__global__ void __launch_bounds__(1024)
scan_add_kernel(int n) {
    __shared__ int pre;
    int blk = blockIdx.x;
    if (threadIdx.x == 0) {
        int s = 0;
        for (int i = 0; i < blk; i++) s += g_bsum[i];
        pre = s;
    }
    __syncthreads();
    int i = blk * 1024 + threadIdx.x;
    if (i < n && blk > 0) g_off[i] += pre;
}

// ---------------- CSR fill: cursor-free, 4B record (src only) ---------------
__global__ void fill_kernel(const int* __restrict__ src, const int* __restrict__ dst, int e) {
    int i = blockIdx.x * blockDim.x + threadIdx.x;
    if (i < e) {
        int s = src[i];
        int d = dst[i];
        int pos = atomicAdd(&g_off[d], 1);
        g_edge[pos] = s;
    }
}

// ---------------- M2 = W @ W and c = W @ b (tiny, side stream, t=0) ----------
__global__ void __launch_bounds__(256)
mat_kernel(const float* __restrict__ W, const float* __restrict__ b) {
    if (blockIdx.x == 16) {
        int j = threadIdx.x;
        if (j < HIDDEN) {
            float acc = 0.f;
            for (int k = 0; k < HIDDEN; k++) acc += W[j * HIDDEN + k] * b[k];
            g_c[j] = acc;
        }
        return;
    }
    __shared__ float Wsh[8][HIDDEN];
    const int jbase = blockIdx.x * 8;
    const int tid = threadIdx.x;
    for (int i = tid; i < 8 * HIDDEN; i += 256)
        Wsh[i >> 7][i & 127] = W[(jbase + (i >> 7)) * HIDDEN + (i & 127)];
    __syncthreads();
    const int m = tid & 127;
    const int half = tid >> 7;
    float acc[4] = {0.f, 0.f, 0.f, 0.f};
    for (int k = 0; k < HIDDEN; k++) {
        float wk = __ldg(&W[k * HIDDEN + m]);
#pragma unroll
        for (int q = 0; q < 4; q++) acc[q] += Wsh[half * 4 + q][k] * wk;
    }
#pragma unroll
    for (int q = 0; q < 4; q++)
        g_M2[(jbase + half * 4 + q) * HIDDEN + m] = acc[q];
}

// ---------------- packed f32x2 helpers ---------------------------------------
__device__ __forceinline__ unsigned long long f32x2_pack(float lo, float hi) {
    unsigned long long r;
    asm("mov.b64 %0, {%1, %2};" : "=l"(r) : "f"(lo), "f"(hi));
    return r;
}
__device__ __forceinline__ void f32x2_fma(unsigned long long& d,
                                          unsigned long long a, unsigned long long b) {
    asm("fma.rn.f32x2 %0, %1, %2, %0;" : "+l"(d) : "l"(a), "l"(b));
}
__device__ __forceinline__ float2 f32x2_unpack(unsigned long long v) {
    float2 r;
    asm("mov.b64 {%0, %1}, %2;" : "=f"(r.x), "=f"(r.y) : "l"(v));
    return r;
}

__device__ __forceinline__ float gelu_exact(float v) {
    return 0.5f * v * (1.0f + erff(v * 0.70710678118654752f));
}

// ---------------- GEMM: z' = dinv * (x @ M2^T + c), fp16 out -----------------
// Runs after scan (needs dinv). FFMA2 at fp32 roofline.
#define GEMM_ROWS 64
#define WT_STRIDE 132
#define AT_STRIDE 66

__global__ void __launch_bounds__(256, 2)
gemmz_kernel(const float* __restrict__ A, const float* __restrict__ M2,
             const float* __restrict__ cvec, int n) {
    extern __shared__ float smem[];
    float* Wt = smem;                          // [k][j], stride 132
    float* At = smem + HIDDEN * WT_STRIDE;     // [k][r], stride 66

    const int tid  = threadIdx.x;
    const int row0 = blockIdx.x * GEMM_ROWS;

    for (int i = tid; i < HIDDEN * HIDDEN; i += 256) {
        int j = i >> 7;
        int k = i & 127;
        Wt[k * WT_STRIDE + j] = M2[i];
    }
    const float4* A4 = reinterpret_cast<const float4*>(A);
    for (int i = tid; i < GEMM_ROWS * 32; i += 256) {
        int r  = i >> 5;
        int c4 = i & 31;
        int gr = row0 + r;
        float4 v = (gr < n) ? A4[(size_t)gr * 32 + c4] : make_float4(0.f, 0.f, 0.f, 0.f);
        At[(4 * c4 + 0) * AT_STRIDE + r] = v.x;
        At[(4 * c4 + 1) * AT_STRIDE + r] = v.y;
        At[(4 * c4 + 2) * AT_STRIDE + r] = v.z;
        At[(4 * c4 + 3) * AT_STRIDE + r] = v.w;
    }
    __syncthreads();

    const int tx = tid & 31;
    const int ty = tid >> 5;

    unsigned long long acc[4][4];
#pragma unroll
    for (int p = 0; p < 4; p++)
#pragma unroll
        for (int c = 0; c < 4; c++) acc[p][c] = 0ull;

    const float* at_base = &At[ty * 8];
    const float* wt_base = &Wt[tx * 4];

#pragma unroll 4
    for (int k = 0; k < HIDDEN; k++) {
        float4 w = *reinterpret_cast<const float4*>(&wt_base[k * WT_STRIDE]);
        unsigned long long w0 = f32x2_pack(w.x, w.x);
        unsigned long long w1 = f32x2_pack(w.y, w.y);
        unsigned long long w2 = f32x2_pack(w.z, w.z);
        unsigned long long w3 = f32x2_pack(w.w, w.w);
        const float* ak = &at_base[k * AT_STRIDE];
        unsigned long long a0 = *reinterpret_cast<const unsigned long long*>(ak + 0);
        unsigned long long a1 = *reinterpret_cast<const unsigned long long*>(ak + 2);
        unsigned long long a2 = *reinterpret_cast<const unsigned long long*>(ak + 4);
        unsigned long long a3 = *reinterpret_cast<const unsigned long long*>(ak + 6);
        f32x2_fma(acc[0][0], a0, w0); f32x2_fma(acc[0][1], a0, w1);
        f32x2_fma(acc[0][2], a0, w2); f32x2_fma(acc[0][3], a0, w3);
        f32x2_fma(acc[1][0], a1, w0); f32x2_fma(acc[1][1], a1, w1);
        f32x2_fma(acc[1][2], a1, w2); f32x2_fma(acc[1][3], a1, w3);
        f32x2_fma(acc[2][0], a2, w0); f32x2_fma(acc[2][1], a2, w1);
        f32x2_fma(acc[2][2], a2, w2); f32x2_fma(acc[2][3], a2, w3);
        f32x2_fma(acc[3][0], a3, w0); f32x2_fma(acc[3][1], a3, w1);
        f32x2_fma(acc[3][2], a3, w2); f32x2_fma(acc[3][3], a3, w3);
    }

    float4 cv = reinterpret_cast<const float4*>(cvec)[tx];
    uint2* zt2 = reinterpret_cast<uint2*>(g_zt);
#pragma unroll
    for (int p = 0; p < 4; p++) {
        int r0 = row0 + ty * 8 + 2 * p;
        float2 c0 = f32x2_unpack(acc[p][0]);
        float2 c1 = f32x2_unpack(acc[p][1]);
        float2 c2 = f32x2_unpack(acc[p][2]);
        float2 c3 = f32x2_unpack(acc[p][3]);
        if (r0 < n) {
            float d0 = __ldg(&g_dinv[r0]);
            __half2 h01 = __floats2half2_rn(d0 * (c0.x + cv.x), d0 * (c1.x + cv.y));
            __half2 h23 = __floats2half2_rn(d0 * (c2.x + cv.z), d0 * (c3.x + cv.w));
            uint2 u;
            u.x = *reinterpret_cast<unsigned*>(&h01);
            u.y = *reinterpret_cast<unsigned*>(&h23);
            zt2[(size_t)r0 * 32 + tx] = u;
        }
        if (r0 + 1 < n) {
            float d1 = __ldg(&g_dinv[r0 + 1]);
            __half2 h01 = __floats2half2_rn(d1 * (c0.y + cv.x), d1 * (c1.y + cv.y));
            __half2 h23 = __floats2half2_rn(d1 * (c2.y + cv.z), d1 * (c3.y + cv.w));
            uint2 u;
            u.x = *reinterpret_cast<unsigned*>(&h01);
            u.y = *reinterpret_cast<unsigned*>(&h23);
            zt2[(size_t)(r0 + 1) * 32 + tx] = u;
        }
    }
}

// ---------------- final: out[i] = gelu(dinv_i * sum_e z'[s] + b) -------------
// Pure sum; 4-edge fp16 pairwise tree (6 HADD2) then one fp32 accumulate.
__global__ void __launch_bounds__(256)
gather_out_kernel(const float* __restrict__ bvec, float* __restrict__ out, int n) {
    int warp = (blockIdx.x * 256 + threadIdx.x) >> 5;
    int lane = threadIdx.x & 31;
    if (warp >= n) return;
    int p  = (warp == 0) ? 0 : __ldg(&g_off[warp - 1]);
    int pe = __ldg(&g_off[warp]);
    const uint2* z2 = reinterpret_cast<const uint2*>(g_zt);
    float4 acc = make_float4(0.f, 0.f, 0.f, 0.f);
#pragma unroll 1
    for (; p + 3 < pe; p += 4) {
        int s0 = __ldg(&g_edge[p]);
        int s1 = __ldg(&g_edge[p + 1]);
        int s2 = __ldg(&g_edge[p + 2]);
        int s3 = __ldg(&g_edge[p + 3]);
        uint2 u0 = __ldg(&z2[(size_t)s0 * 32 + lane]);
        uint2 u1 = __ldg(&z2[(size_t)s1 * 32 + lane]);
        uint2 u2 = __ldg(&z2[(size_t)s2 * 32 + lane]);
        uint2 u3 = __ldg(&z2[(size_t)s3 * 32 + lane]);
        // fp16 pairwise tree: (z0+z1)+(z2+z3) per half2 register
        __half2 px = __hadd2(__hadd2(*reinterpret_cast<__half2*>(&u0.x),
                                     *reinterpret_cast<__half2*>(&u1.x)),
                             __hadd2(*reinterpret_cast<__half2*>(&u2.x),
                                     *reinterpret_cast<__half2*>(&u3.x)));
        __half2 py = __hadd2(__hadd2(*reinterpret_cast<__half2*>(&u0.y),
                                     *reinterpret_cast<__half2*>(&u1.y)),
                             __hadd2(*reinterpret_cast<__half2*>(&u2.y),
                                     *reinterpret_cast<__half2*>(&u3.y)));
        float2 fx = __half22float2(px);
        float2 fy = __half22float2(py);
        acc.x += fx.x; acc.y += fx.y;
        acc.z += fy.x; acc.w += fy.y;
    }
    for (; p < pe; p++) {
        int s0 = __ldg(&g_edge[p]);
        uint2 u0 = __ldg(&z2[(size_t)s0 * 32 + lane]);
        float2 a0 = __half22float2(*reinterpret_cast<__half2*>(&u0.x));
        float2 b0 = __half22float2(*reinterpret_cast<__half2*>(&u0.y));
        acc.x += a0.x; acc.y += a0.y;
        acc.z += b0.x; acc.w += b0.y;
    }
    float di = __ldg(&g_dinv[warp]);
    float4 bv = reinterpret_cast<const float4*>(bvec)[lane];
    float4 o;
    o.x = gelu_exact(di * acc.x + bv.x);
    o.y = gelu_exact(di * acc.y + bv.y);
    o.z = gelu_exact(di * acc.z + bv.z);
    o.w = gelu_exact(di * acc.w + bv.w);
    reinterpret_cast<float4*>(out)[(size_t)warp * 32 + lane] = o;
}

// ---------------- launch -----------------------------------------------------
extern "C" void kernel_launch(void* const* d_in, const int* in_sizes, int n_in,
                              void* d_out, int out_size) {
    const float* x = (const float*)d_in[0];
    const float* W = (const float*)d_in[1];
    const float* b = (const float*)d_in[2];
    const int* ei  = (const int*)d_in[3];

    const int n = in_sizes[0] / HIDDEN;   // 50000
    const int e = in_sizes[3] / 2;        // 800000
    const int* src = ei;
    const int* dst = ei + e;

    float* out = (float*)d_out;

    static float* p_M2  = nullptr;
    static float* p_c   = nullptr;
    static int*   p_deg = nullptr;
    static cudaStream_t s2 = nullptr;
    static cudaEvent_t ev_fork = nullptr, ev_scan = nullptr, ev_join = nullptr;
    if (!p_M2) {
        cudaGetSymbolAddress((void**)&p_M2, g_M2);
        cudaGetSymbolAddress((void**)&p_c, g_c);
        cudaGetSymbolAddress((void**)&p_deg, g_degi);
        cudaStreamCreateWithFlags(&s2, cudaStreamNonBlocking);
        cudaEventCreateWithFlags(&ev_fork, cudaEventDisableTiming);
        cudaEventCreateWithFlags(&ev_scan, cudaEventDisableTiming);
        cudaEventCreateWithFlags(&ev_join, cudaEventDisableTiming);
        const size_t smem_bytes = (HIDDEN * WT_STRIDE + HIDDEN * AT_STRIDE) * sizeof(float);
        cudaFuncSetAttribute(gemmz_kernel,
                             cudaFuncAttributeMaxDynamicSharedMemorySize, (int)smem_bytes);
    }
    const size_t smem_bytes = (HIDDEN * WT_STRIDE + HIDDEN * AT_STRIDE) * sizeof(float);

    // ---- side stream: mat at t=0 (needs only W,b) ---------------------------
    cudaEventRecord(ev_fork, 0);
    cudaStreamWaitEvent(s2, ev_fork, 0);
    mat_kernel<<<17, 256, 0, s2>>>(W, b);

    // ---- main stream: CSR chain ---------------------------------------------
    cudaMemsetAsync(p_deg, 0, (size_t)n * sizeof(int));
    deg_kernel<<<(e + 255) / 256, 256>>>(dst, e);
    int nscan = (n + 1023) / 1024;  // 49
    scan_block_kernel<<<nscan, 1024>>>(n);
    scan_add_kernel<<<nscan, 1024>>>(n);
    cudaEventRecord(ev_scan, 0);

    // ---- side stream: gemmz after scan (needs dinv) + mat -------------------
    cudaStreamWaitEvent(s2, ev_scan, 0);
    const int gemm_blocks = (n + GEMM_ROWS - 1) / GEMM_ROWS;
    gemmz_kernel<<<gemm_blocks, 256, smem_bytes, s2>>>(x, p_M2, p_c, n);
    cudaEventRecord(ev_join, s2);

    // ---- main stream: fill (concurrent with gemmz), then join + gather ------
    fill_kernel<<<(e + 255) / 256, 256>>>(src, dst, e);
    cudaStreamWaitEvent(0, ev_join, 0);
    unsigned gthreads = (unsigned)n * 32u;
    gather_out_kernel<<<(gthreads + 255) / 256, 256>>>(b, out, n);
}